// round 7
// baseline (speedup 1.0000x reference)
#include <cuda_runtime.h>
#include <stdint.h>

#define BATCH   8192
#define IN_DIM  1024
#define N_HID   2048
#define OUT_DIM 256
#define S2      3072
#define NT1     8         // 1024/128 source tiles (layer1)
#define NT2     24        // 3072/128 source tiles (layer2)
#define ECAP    24        // Bin(128,.05): mean 6.4, sd 2.47 -> 7.1 sigma
#define BT      64        // batch tile: 32 lanes x float2

// ---- scratch (static device globals: allocation-free) ----
__device__ float    g_xT[(size_t)IN_DIM * BATCH];                 // w * x, transposed
__device__ float    g_hT[(size_t)N_HID * BATCH];                  // w * hidden, transposed
__device__ uint16_t g_et1[(size_t)NT1 * N_HID * ECAP];            // [tile][row][ECAP]
__device__ uint16_t g_et2[(size_t)NT2 * OUT_DIM * ECAP];
__device__ uint16_t g_ct1[(size_t)NT1 * N_HID];                   // [tile][row]
__device__ uint16_t g_ct2[(size_t)NT2 * OUT_DIM];

// ------------------------------------------------------------------
// Build tile-major edge lists. Entry = s_in_tile*4 + (code-1) (<=511),
// shifted to a byte offset (<<8) at use in 32-bit regs. Deterministic.
// ------------------------------------------------------------------
__global__ void build_edges_kernel(const int* __restrict__ mat) {
    int row  = blockIdx.x;
    int lane = threadIdx.x & 31, warp = threadIdx.x >> 5;  // 256 thr
    bool is2 = (row >= N_HID);
    int ntiles = is2 ? NT2 : NT1;
    int rows   = is2 ? OUT_DIM : N_HID;
    int rloc   = is2 ? row - N_HID : row;
    const int* mrow = mat + (size_t)row * S2;
    uint16_t* et = is2 ? g_et2 : g_et1;
    uint16_t* ct = is2 ? g_ct2 : g_ct1;
    unsigned lt = (1u << lane) - 1u;

    for (int t = warp; t < ntiles; t += 8) {
        int cnt = 0;
        uint16_t* dst = et + ((size_t)t * rows + rloc) * ECAP;
        for (int c = 0; c < 4; ++c) {      // 128-wide tile = 4 ballots
            int code = mrow[t * 128 + c * 32 + lane];
            unsigned m = __ballot_sync(0xffffffffu, code != 0);
            int p = cnt + __popc(m & lt);
            if (code && p < ECAP)
                dst[p] = (uint16_t)(((c * 32 + lane) << 2) | (code - 1));
            cnt += __popc(m);
        }
        if (lane == 0) ct[(size_t)t * rows + rloc] = (uint16_t)(cnt < ECAP ? cnt : ECAP);
    }
}

// ------------------------------------------------------------------
// Transpose x [B][IN] -> g_xT [IN][B], pre-scaled by w.
// ------------------------------------------------------------------
__global__ void transpose_kernel(const float* __restrict__ x, const float* __restrict__ wp) {
    __shared__ float tile[32][33];
    float w = *wp;
    int i0 = blockIdx.x * 32, b0 = blockIdx.y * 32;
    int tx = threadIdx.x, ty = threadIdx.y;   // 32 x 8
#pragma unroll
    for (int k = 0; k < 32; k += 8)
        tile[ty + k][tx] = w * x[(size_t)(b0 + ty + k) * IN_DIM + i0 + tx];
    __syncthreads();
#pragma unroll
    for (int k = 0; k < 32; k += 8)
        g_xT[(size_t)(i0 + ty + k) * BATCH + b0 + tx] = tile[tx][ty + k];
}

__device__ __forceinline__ float ftanh(float x) {
    float r; asm("tanh.approx.f32 %0, %1;" : "=f"(r) : "f"(x)); return r;
}
__device__ __forceinline__ void addp(unsigned long long& a, unsigned long long b) {
    asm("add.rn.f32x2 %0, %0, %1;" : "+l"(a) : "l"(b));
}

// ------------------------------------------------------------------
// Layer kernel: 1024 threads (32 warps), 1 CTA/SM.
// planes[128 srcs][4 acts][64 cols] fp32 = 128KB, single-buffered.
// Edges double-buffered in smem, staged from tile-major global.
// Edge payload: float2 per lane (LDS.64) + add.rn.f32x2.
// ------------------------------------------------------------------
template<int NT, int NPW, int ROWS, bool IS_L1>
__global__ void __launch_bounds__(1024, 1)
layer_kernel(const float* __restrict__ wp, float* __restrict__ dout) {
    constexpr int NODES = 32 * NPW;
    extern __shared__ char smraw[];
    float*    planes = (float*)smraw;                                  // 128KB
    uint16_t* s_ed0  = (uint16_t*)(smraw + 128 * 4 * BT * 4);
    uint16_t* s_ed1  = s_ed0 + NODES * ECAP;
    uint16_t* s_cn0  = s_ed1 + NODES * ECAP;
    uint16_t* s_cn1  = s_cn0 + NODES;

    int b0   = blockIdx.x * BT;
    int r0   = blockIdx.y * NODES;
    int tid  = threadIdx.x;
    int warp = tid >> 5, lane = tid & 31;

    const uint16_t* get = IS_L1 ? g_et1 : g_et2;
    const uint16_t* gct = IS_L1 ? g_ct1 : g_ct2;

#define STAGE(TT, ED, CN)                                                          \
    {                                                                              \
        const uint4* esrc = (const uint4*)(get + ((size_t)(TT) * ROWS + r0) * ECAP); \
        uint4* edst = (uint4*)(ED);                                                \
        for (int i = tid; i < NODES * ECAP / 8; i += 1024) edst[i] = __ldg(esrc + i); \
        const uint4* csrc = (const uint4*)(gct + (size_t)(TT) * ROWS + r0);        \
        uint4* cdst = (uint4*)(CN);                                                \
        for (int i = tid; i < NODES / 8; i += 1024) cdst[i] = __ldg(csrc + i);     \
    }

    STAGE(0, s_ed0, s_cn0);

    unsigned long long acc[NPW];
#pragma unroll
    for (int n = 0; n < NPW; ++n) acc[n] = 0ULL;

    // fill tasks: 128 srcs x 16 float4-chunks = 2048, 2 per thread
    float4 pf[2];
#define LOADF(T)                                                                \
    {                                                                           \
        _Pragma("unroll")                                                       \
        for (int k = 0; k < 2; ++k) {                                           \
            int idx = tid + (k << 10);                                          \
            int ls = idx >> 4, c4 = (idx & 15) << 2;                            \
            int s0 = (T) * 128;                                                 \
            const float* gb = (IS_L1 || s0 < IN_DIM)                            \
                ? g_xT + (size_t)s0 * BATCH                                     \
                : g_hT + (size_t)(s0 - IN_DIM) * BATCH;                         \
            pf[k] = __ldg((const float4*)(gb + (size_t)ls * BATCH + b0 + c4));  \
        }                                                                       \
    }

    LOADF(0);
    __syncthreads();   // staging visible

    const char* pbase = (const char*)planes + lane * 8;

    for (int t = 0; t < NT; ++t) {
        // ---- fill planes(t) from prefetched regs ----
#pragma unroll
        for (int k = 0; k < 2; ++k) {
            int idx = tid + (k << 10);
            int ls = idx >> 4, c4 = (idx & 15) << 2;
            float4 xv = pf[k];
            float4 p1, p2, p3;
            p1.x = fmaxf(xv.x, 0.0f); p1.y = fmaxf(xv.y, 0.0f);
            p1.z = fmaxf(xv.z, 0.0f); p1.w = fmaxf(xv.w, 0.0f);
            p2.x = ftanh(xv.x); p2.y = ftanh(xv.y); p2.z = ftanh(xv.z); p2.w = ftanh(xv.w);
            p3.x = fmaf(0.5f, ftanh(0.5f * xv.x), 0.5f);
            p3.y = fmaf(0.5f, ftanh(0.5f * xv.y), 0.5f);
            p3.z = fmaf(0.5f, ftanh(0.5f * xv.z), 0.5f);
            p3.w = fmaf(0.5f, ftanh(0.5f * xv.w), 0.5f);
            float* pr = planes + (size_t)(ls * 4) * BT + c4;
            *(float4*)(pr)          = xv;
            *(float4*)(pr + BT)     = p1;
            *(float4*)(pr + 2 * BT) = p2;
            *(float4*)(pr + 3 * BT) = p3;
        }
        // stage edges(t+1) into the other buffer
        if (t + 1 < NT) {
            if (t & 1) STAGE(t + 1, s_ed0, s_cn0)
            else       STAGE(t + 1, s_ed1, s_cn1)
        }
        __syncthreads();   // planes(t) ready

        // prefetch next tile's fill data (consumed after next sync)
        if (t + 1 < NT) LOADF(t + 1);

        // ---- edge phase: pairwise entries, independent LDS.64 ----
        const uint32_t* ebuf = (const uint32_t*)((t & 1) ? s_ed1 : s_ed0);
        const uint16_t* cbuf = (t & 1) ? s_cn1 : s_cn0;
#pragma unroll
        for (int n = 0; n < NPW; ++n) {
            int rl = warp * NPW + n;
            int cnt = cbuf[rl];
            const uint32_t* ep = ebuf + rl * (ECAP / 2);
            int np = cnt >> 1;
#pragma unroll 2
            for (int j = 0; j < np; ++j) {
                uint32_t u = ep[j];
                unsigned long long a = *(const unsigned long long*)(pbase + ((u & 0xffffu) << 8));
                unsigned long long b = *(const unsigned long long*)(pbase + ((u >> 16) << 8));
                addp(acc[n], a);
                addp(acc[n], b);
            }
            if (cnt & 1) {
                uint32_t u = ep[np] & 0xffffu;
                addp(acc[n], *(const unsigned long long*)(pbase + (u << 8)));
            }
        }
        __syncthreads();   // edge(t) done -> planes reusable
    }

    // ---- epilogue ----
    if (IS_L1) {
        float w = *wp;   // g_hT holds w * hidden for layer2's fill
#pragma unroll
        for (int n = 0; n < NPW; ++n) {
            int r = r0 + warp * NPW + n;
            float2 v = *(float2*)&acc[n];
            float2 q; q.x = w * v.x; q.y = w * v.y;
            *(float2*)&g_hT[(size_t)r * BATCH + b0 + lane * 2] = q;
        }
    } else {
#pragma unroll
        for (int n = 0; n < NPW; ++n) {
            int r = r0 + warp * NPW + n;
            float2 v = *(float2*)&acc[n];
            dout[(size_t)(b0 + lane * 2 + 0) * OUT_DIM + r] = v.x;
            dout[(size_t)(b0 + lane * 2 + 1) * OUT_DIM + r] = v.y;
        }
    }
#undef STAGE
#undef LOADF
}

// smem: planes 128KB + 2 edge buffers + 2 count buffers
#define SMEM_L1 (128 * 4 * BT * 4 + 2 * 512 * ECAP * 2 + 2 * 512 * 2)   // 182272
#define SMEM_L2 (128 * 4 * BT * 4 + 2 * 256 * ECAP * 2 + 2 * 256 * 2)   // 156672

extern "C" void kernel_launch(void* const* d_in, const int* in_sizes, int n_in,
                              void* d_out, int out_size) {
    const float* x   = (const float*)d_in[0];
    const float* wp  = (const float*)d_in[1];
    const int*   mat = (const int*)d_in[2];
    float*       out = (float*)d_out;

    // L1: NODES=512 (NPW=16) -> grid (128, 4); fill duplication 4
    auto k1 = layer_kernel<NT1, 16, N_HID, true>;
    // L2: NODES=256 (NPW=8)  -> grid (128, 1); no duplication
    auto k2 = layer_kernel<NT2, 8, OUT_DIM, false>;

    cudaFuncSetAttribute(k1, cudaFuncAttributeMaxDynamicSharedMemorySize, SMEM_L1);
    cudaFuncSetAttribute(k2, cudaFuncAttributeMaxDynamicSharedMemorySize, SMEM_L2);

    build_edges_kernel<<<N_HID + OUT_DIM, 256>>>(mat);
    transpose_kernel<<<dim3(IN_DIM / 32, BATCH / 32), dim3(32, 8)>>>(x, wp);

    k1<<<dim3(BATCH / BT, N_HID / 512), 1024, SMEM_L1>>>(wp, nullptr);
    k2<<<dim3(BATCH / BT, OUT_DIM / 256), 1024, SMEM_L2>>>(wp, out);
}

// round 8
// speedup vs baseline: 1.2543x; 1.2543x over previous
#include <cuda_runtime.h>
#include <stdint.h>

#define BATCH   8192
#define IN_DIM  1024
#define N_HID   2048
#define OUT_DIM 256
#define S2      3072
#define NT1     16        // 1024/64  source tiles (layer1, 64-wide)
#define NT2     24        // 3072/128 source tiles (layer2, 128-wide)
#define ECAP1   16        // Bin(64,.05):  mean 3.2, 7.3 sigma
#define ECAP2   24        // Bin(128,.05): mean 6.4, 7.1 sigma
#define BT      64        // batch tile: 32 lanes x float2

// ---- scratch (static device globals: allocation-free) ----
__device__ float    g_xT[(size_t)IN_DIM * BATCH];                 // w * x, transposed
__device__ float    g_hT[(size_t)N_HID * BATCH];                  // w * hidden, transposed
__device__ uint16_t g_et1[(size_t)NT1 * N_HID * ECAP1];           // [tile][row][ECAP1]
__device__ uint16_t g_et2[(size_t)NT2 * OUT_DIM * ECAP2];
__device__ uint16_t g_ct1[(size_t)NT1 * N_HID];                   // [tile][row]
__device__ uint16_t g_ct2[(size_t)NT2 * OUT_DIM];

// ------------------------------------------------------------------
// Build tile-major edge lists. Entry = s_in_tile*4 + (code-1); layer
// kernel shifts <<8 (plane act-row = 64 floats = 256B). Deterministic.
// ------------------------------------------------------------------
__global__ void build_edges_kernel(const int* __restrict__ mat) {
    int row  = blockIdx.x;
    int lane = threadIdx.x & 31, warp = threadIdx.x >> 5;  // 256 thr
    bool is2 = (row >= N_HID);
    int ntiles = is2 ? NT2 : NT1;
    int tw     = is2 ? 128 : 64;         // tile width
    int ecap   = is2 ? ECAP2 : ECAP1;
    int rows   = is2 ? OUT_DIM : N_HID;
    int rloc   = is2 ? row - N_HID : row;
    const int* mrow = mat + (size_t)row * S2;
    uint16_t* et = is2 ? g_et2 : g_et1;
    uint16_t* ct = is2 ? g_ct2 : g_ct1;
    unsigned lt = (1u << lane) - 1u;

    for (int t = warp; t < ntiles; t += 8) {
        int cnt = 0;
        uint16_t* dst = et + ((size_t)t * rows + rloc) * ecap;
        for (int c = 0; c < tw / 32; ++c) {
            int code = mrow[t * tw + c * 32 + lane];
            unsigned m = __ballot_sync(0xffffffffu, code != 0);
            int p = cnt + __popc(m & lt);
            if (code && p < ecap)
                dst[p] = (uint16_t)(((c * 32 + lane) << 2) | (code - 1));
            cnt += __popc(m);
        }
        if (lane == 0) ct[(size_t)t * rows + rloc] = (uint16_t)(cnt < ecap ? cnt : ecap);
    }
}

// ------------------------------------------------------------------
// Transpose x [B][IN] -> g_xT [IN][B], pre-scaled by w.
// ------------------------------------------------------------------
__global__ void transpose_kernel(const float* __restrict__ x, const float* __restrict__ wp) {
    __shared__ float tile[32][33];
    float w = *wp;
    int i0 = blockIdx.x * 32, b0 = blockIdx.y * 32;
    int tx = threadIdx.x, ty = threadIdx.y;   // 32 x 8
#pragma unroll
    for (int k = 0; k < 32; k += 8)
        tile[ty + k][tx] = w * x[(size_t)(b0 + ty + k) * IN_DIM + i0 + tx];
    __syncthreads();
#pragma unroll
    for (int k = 0; k < 32; k += 8)
        g_xT[(size_t)(i0 + ty + k) * BATCH + b0 + tx] = tile[tx][ty + k];
}

__device__ __forceinline__ float ftanh(float x) {
    float r; asm("tanh.approx.f32 %0, %1;" : "=f"(r) : "f"(x)); return r;
}
__device__ __forceinline__ void addp(unsigned long long& a, unsigned long long b) {
    asm("add.rn.f32x2 %0, %0, %1;" : "+l"(a) : "l"(b));
}

// ------------------------------------------------------------------
// Layer kernel. THREADS threads, OCC CTAs/SM.
// planes[SRCS][4 acts][BT=64] fp32; edges double-buffered in smem,
// staged from tile-major global. Per edge: LDS.64 + add.rn.f32x2.
// (Edge pair loop intentionally left un-pragma'd: R7 showed unroll-2
//  breaks ptxas scheduling here, +52% on this loop.)
// ------------------------------------------------------------------
template<int THREADS, int OCC, int NT, int SRCS, int NPW, int ECAP, int ROWS, bool IS_L1>
__global__ void __launch_bounds__(THREADS, OCC)
layer_kernel(const float* __restrict__ wp, float* __restrict__ dout) {
    constexpr int NODES = (THREADS / 32) * NPW;
    constexpr int FILL_K = SRCS * (BT / 4) / THREADS;   // float4 chunks per thread
    extern __shared__ char smraw[];
    float*    planes = (float*)smraw;                           // SRCS*4*BT*4 bytes
    uint16_t* s_ed0  = (uint16_t*)(smraw + SRCS * 4 * BT * 4);
    uint16_t* s_ed1  = s_ed0 + NODES * ECAP;
    uint16_t* s_cn0  = s_ed1 + NODES * ECAP;
    uint16_t* s_cn1  = s_cn0 + NODES;

    int b0   = blockIdx.x * BT;
    int r0   = blockIdx.y * NODES;
    int tid  = threadIdx.x;
    int warp = tid >> 5, lane = tid & 31;

    const uint16_t* get = IS_L1 ? g_et1 : g_et2;
    const uint16_t* gct = IS_L1 ? g_ct1 : g_ct2;

#define STAGE(TT, ED, CN)                                                          \
    {                                                                              \
        const uint4* esrc = (const uint4*)(get + ((size_t)(TT) * ROWS + r0) * ECAP); \
        uint4* edst = (uint4*)(ED);                                                \
        for (int i = tid; i < NODES * ECAP / 8; i += THREADS) edst[i] = __ldg(esrc + i); \
        const uint4* csrc = (const uint4*)(gct + (size_t)(TT) * ROWS + r0);        \
        uint4* cdst = (uint4*)(CN);                                                \
        for (int i = tid; i < NODES / 8; i += THREADS) cdst[i] = __ldg(csrc + i);  \
    }

    STAGE(0, s_ed0, s_cn0);

    unsigned long long acc[NPW];
#pragma unroll
    for (int n = 0; n < NPW; ++n) acc[n] = 0ULL;

    float4 pf[FILL_K];
#define LOADF(T)                                                                \
    {                                                                           \
        _Pragma("unroll")                                                       \
        for (int k = 0; k < FILL_K; ++k) {                                      \
            int idx = tid + k * THREADS;                                        \
            int ls = idx >> 4, c4 = (idx & 15) << 2;                            \
            int s0 = (T) * SRCS;                                                \
            const float* gb = (IS_L1 || s0 < IN_DIM)                            \
                ? g_xT + (size_t)s0 * BATCH                                     \
                : g_hT + (size_t)(s0 - IN_DIM) * BATCH;                         \
            pf[k] = __ldg((const float4*)(gb + (size_t)ls * BATCH + b0 + c4));  \
        }                                                                       \
    }

    LOADF(0);
    __syncthreads();   // staging visible

    const char* pbase = (const char*)planes + lane * 8;

    for (int t = 0; t < NT; ++t) {
        // ---- fill planes(t) from prefetched regs ----
#pragma unroll
        for (int k = 0; k < FILL_K; ++k) {
            int idx = tid + k * THREADS;
            int ls = idx >> 4, c4 = (idx & 15) << 2;
            float4 xv = pf[k];
            float4 p1, p2, p3;
            p1.x = fmaxf(xv.x, 0.0f); p1.y = fmaxf(xv.y, 0.0f);
            p1.z = fmaxf(xv.z, 0.0f); p1.w = fmaxf(xv.w, 0.0f);
            p2.x = ftanh(xv.x); p2.y = ftanh(xv.y); p2.z = ftanh(xv.z); p2.w = ftanh(xv.w);
            p3.x = fmaf(0.5f, ftanh(0.5f * xv.x), 0.5f);
            p3.y = fmaf(0.5f, ftanh(0.5f * xv.y), 0.5f);
            p3.z = fmaf(0.5f, ftanh(0.5f * xv.z), 0.5f);
            p3.w = fmaf(0.5f, ftanh(0.5f * xv.w), 0.5f);
            float* pr = planes + (size_t)(ls * 4) * BT + c4;
            *(float4*)(pr)          = xv;
            *(float4*)(pr + BT)     = p1;
            *(float4*)(pr + 2 * BT) = p2;
            *(float4*)(pr + 3 * BT) = p3;
        }
        // stage edges(t+1) into the other buffer
        if (t + 1 < NT) {
            if (t & 1) STAGE(t + 1, s_ed0, s_cn0)
            else       STAGE(t + 1, s_ed1, s_cn1)
        }
        __syncthreads();   // planes(t) ready

        // prefetch next tile's fill data (consumed after next sync)
        if (t + 1 < NT) LOADF(t + 1);

        // ---- edge phase: pairwise entries, independent LDS.64 ----
        const uint32_t* ebuf = (const uint32_t*)((t & 1) ? s_ed1 : s_ed0);
        const uint16_t* cbuf = (t & 1) ? s_cn1 : s_cn0;
#pragma unroll
        for (int n = 0; n < NPW; ++n) {
            int rl = warp * NPW + n;
            int cnt = cbuf[rl];
            const uint32_t* ep = ebuf + rl * (ECAP / 2);
            int np = cnt >> 1;
            for (int j = 0; j < np; ++j) {
                uint32_t u = ep[j];
                unsigned long long a = *(const unsigned long long*)(pbase + ((u & 0xffffu) << 8));
                unsigned long long b = *(const unsigned long long*)(pbase + ((u >> 16) << 8));
                addp(acc[n], a);
                addp(acc[n], b);
            }
            if (cnt & 1) {
                uint32_t u = ep[np] & 0xffffu;
                addp(acc[n], *(const unsigned long long*)(pbase + (u << 8)));
            }
        }
        __syncthreads();   // edge(t) done -> planes reusable
    }

    // ---- epilogue ----
    if (IS_L1) {
        float w = *wp;   // g_hT holds w * hidden for layer2's fill
#pragma unroll
        for (int n = 0; n < NPW; ++n) {
            int r = r0 + warp * NPW + n;
            float2 v = *(float2*)&acc[n];
            float2 q; q.x = w * v.x; q.y = w * v.y;
            *(float2*)&g_hT[(size_t)r * BATCH + b0 + lane * 2] = q;
        }
    } else {
#pragma unroll
        for (int n = 0; n < NPW; ++n) {
            int r = r0 + warp * NPW + n;
            float2 v = *(float2*)&acc[n];
            dout[(size_t)(b0 + lane * 2 + 0) * OUT_DIM + r] = v.x;
            dout[(size_t)(b0 + lane * 2 + 1) * OUT_DIM + r] = v.y;
        }
    }
#undef STAGE
#undef LOADF
}

// L1: 512 thr, 2 CTA/SM, SRCS=64:  planes 64KB + 2*256*16*2 + 2*256*2 = 82944
// L2: 1024 thr, 1 CTA/SM, SRCS=128: planes 128KB + 2*256*24*2 + 2*256*2 = 156672
#define SMEM_L1 (64 * 4 * BT * 4 + 2 * 256 * ECAP1 * 2 + 2 * 256 * 2)
#define SMEM_L2 (128 * 4 * BT * 4 + 2 * 256 * ECAP2 * 2 + 2 * 256 * 2)

extern "C" void kernel_launch(void* const* d_in, const int* in_sizes, int n_in,
                              void* d_out, int out_size) {
    const float* x   = (const float*)d_in[0];
    const float* wp  = (const float*)d_in[1];
    const int*   mat = (const int*)d_in[2];
    float*       out = (float*)d_out;

    // L1: NODES=256 (16 warps x 16), grid (128, 8), 2 CTAs/SM overlap
    auto k1 = layer_kernel<512, 2, NT1, 64, 16, ECAP1, N_HID, true>;
    // L2: NODES=256 (32 warps x 8), grid (128, 1)  [R6 config, unchanged]
    auto k2 = layer_kernel<1024, 1, NT2, 128, 8, ECAP2, OUT_DIM, false>;

    cudaFuncSetAttribute(k1, cudaFuncAttributeMaxDynamicSharedMemorySize, SMEM_L1);
    cudaFuncSetAttribute(k2, cudaFuncAttributeMaxDynamicSharedMemorySize, SMEM_L2);

    build_edges_kernel<<<N_HID + OUT_DIM, 256>>>(mat);
    transpose_kernel<<<dim3(IN_DIM / 32, BATCH / 32), dim3(32, 8)>>>(x, wp);

    k1<<<dim3(BATCH / BT, N_HID / 256), 512, SMEM_L1>>>(wp, nullptr);
    k2<<<dim3(BATCH / BT, OUT_DIM / 256), 1024, SMEM_L2>>>(wp, out);
}

// round 9
// speedup vs baseline: 1.4160x; 1.1289x over previous
#include <cuda_runtime.h>
#include <cuda_fp16.h>
#include <stdint.h>

#define BATCH   8192
#define IN_DIM  1024
#define N_HID   2048
#define OUT_DIM 256
#define S2      3072
#define NT1     16        // 1024/64  source tiles (layer1, 64-wide)
#define NT2     24        // 3072/128 source tiles (layer2, 128-wide)
#define ECAP1   16        // Bin(64,.05):  mean 3.2, 7.3 sigma
#define ECAP2   24        // Bin(128,.05): mean 6.4, 7.1 sigma
#define BT2     64        // layer2 batch tile
#define BT1     128       // layer1 batch tile

// ---- scratch (static device globals: allocation-free) ----
__device__ float    g_xT[(size_t)IN_DIM * BATCH];                 // w * x, transposed (L2 fill)
__device__ float    g_hT[(size_t)N_HID * BATCH];                  // w * hidden, transposed
__device__ __half   g_pl[(size_t)IN_DIM * 4 * BATCH];             // 4 act planes of w*x, fp16, 64MB
__device__ uint16_t g_et1[(size_t)NT1 * N_HID * ECAP1];           // [tile][row][ECAP1]
__device__ uint16_t g_et2[(size_t)NT2 * OUT_DIM * ECAP2];
__device__ uint16_t g_ct1[(size_t)NT1 * N_HID];                   // [tile][row]
__device__ uint16_t g_ct2[(size_t)NT2 * OUT_DIM];

// ------------------------------------------------------------------
// Build tile-major edge lists. Entry = s_in_tile*4 + (code-1); layer
// kernels shift <<8 (plane row = 256B in both layers). Deterministic.
// ------------------------------------------------------------------
__global__ void build_edges_kernel(const int* __restrict__ mat) {
    int row  = blockIdx.x;
    int lane = threadIdx.x & 31, warp = threadIdx.x >> 5;  // 256 thr
    bool is2 = (row >= N_HID);
    int ntiles = is2 ? NT2 : NT1;
    int tw     = is2 ? 128 : 64;         // tile width
    int ecap   = is2 ? ECAP2 : ECAP1;
    int rows   = is2 ? OUT_DIM : N_HID;
    int rloc   = is2 ? row - N_HID : row;
    const int* mrow = mat + (size_t)row * S2;
    uint16_t* et = is2 ? g_et2 : g_et1;
    uint16_t* ct = is2 ? g_ct2 : g_ct1;
    unsigned lt = (1u << lane) - 1u;

    for (int t = warp; t < ntiles; t += 8) {
        int cnt = 0;
        uint16_t* dst = et + ((size_t)t * rows + rloc) * ecap;
        for (int c = 0; c < tw / 32; ++c) {
            int code = mrow[t * tw + c * 32 + lane];
            unsigned m = __ballot_sync(0xffffffffu, code != 0);
            int p = cnt + __popc(m & lt);
            if (code && p < ecap)
                dst[p] = (uint16_t)(((c * 32 + lane) << 2) | (code - 1));
            cnt += __popc(m);
        }
        if (lane == 0) ct[(size_t)t * rows + rloc] = (uint16_t)(cnt < ecap ? cnt : ecap);
    }
}

__device__ __forceinline__ float ftanh(float x) {
    float r; asm("tanh.approx.f32 %0, %1;" : "=f"(r) : "f"(x)); return r;
}
__device__ __forceinline__ void addp(unsigned long long& a, unsigned long long b) {
    asm("add.rn.f32x2 %0, %0, %1;" : "+l"(a) : "l"(b));
}
__device__ __forceinline__ unsigned long long f2u(float2 v) {
    unsigned long long r; asm("mov.b64 %0, {%1,%2};" : "=l"(r) : "f"(v.x), "f"(v.y)); return r;
}

// ------------------------------------------------------------------
// act_kernel: transpose x, scale by w, write g_xT (fp32, for L2 fill)
// and all 4 activation planes g_pl (fp16, for L1 fill copies).
// ------------------------------------------------------------------
__global__ void act_kernel(const float* __restrict__ x, const float* __restrict__ wp) {
    __shared__ float tile[32][33];
    float w = *wp;
    int i0 = blockIdx.x * 32, b0 = blockIdx.y * 32;
    int tx = threadIdx.x, ty = threadIdx.y;   // 32 x 8
#pragma unroll
    for (int k = 0; k < 32; k += 8)
        tile[ty + k][tx] = w * x[(size_t)(b0 + ty + k) * IN_DIM + i0 + tx];
    __syncthreads();
#pragma unroll
    for (int k = 0; k < 32; k += 8) {
        int s = i0 + ty + k;
        int b = b0 + tx;
        float v = tile[tx][ty + k];
        g_xT[(size_t)s * BATCH + b] = v;
        size_t base = ((size_t)s * 4) * BATCH + b;
        g_pl[base]             = __float2half_rn(v);
        g_pl[base + BATCH]     = __float2half_rn(fmaxf(v, 0.0f));
        g_pl[base + 2 * BATCH] = __float2half_rn(ftanh(v));
        g_pl[base + 3 * BATCH] = __float2half_rn(fmaf(0.5f, ftanh(0.5f * v), 0.5f));
    }
}

// ------------------------------------------------------------------
// Layer 1: 1024 threads, fp16 planes double-buffered (one barrier per
// tile). Fill = pure 16B copy from g_pl. Edge: LDS.64 (4 halves) ->
// 2x half2->float2 cvt -> f32x2 adds. NODES=256 (NPW=8), BT=128.
// ------------------------------------------------------------------
__global__ void __launch_bounds__(1024, 1)
layer1_kernel(const float* __restrict__ wp) {
    extern __shared__ char smraw[];
    __half*   pl0   = (__half*)smraw;                 // 64KB
    __half*   pl1   = pl0 + 64 * 4 * BT1;             // 64KB
    uint16_t* s_ed0 = (uint16_t*)(smraw + 131072);    // 256*16
    uint16_t* s_ed1 = s_ed0 + 256 * ECAP1;
    uint16_t* s_cn0 = s_ed1 + 256 * ECAP1;
    uint16_t* s_cn1 = s_cn0 + 256;

    int r0   = blockIdx.x * 256;
    int b0   = blockIdx.y * BT1;
    int tid  = threadIdx.x;
    int warp = tid >> 5, lane = tid & 31;

#define STAGE1(TT, ED, CN)                                                           \
    {                                                                                \
        const uint4* esrc = (const uint4*)(g_et1 + ((size_t)(TT) * N_HID + r0) * ECAP1); \
        uint4* edst = (uint4*)(ED);                                                  \
        if (tid < 512) edst[tid] = __ldg(esrc + tid);                                \
        const uint4* csrc = (const uint4*)(g_ct1 + (size_t)(TT) * N_HID + r0);       \
        uint4* cdst = (uint4*)(CN);                                                  \
        if (tid < 32) cdst[tid] = __ldg(csrc + tid);                                 \
    }

    // copy tile TT's 256 plane-rows (s0*4 contiguous rows of g_pl) x 256B
#define FILL1(TT, BUF)                                                               \
    {                                                                                \
        _Pragma("unroll")                                                            \
        for (int k = 0; k < 4; ++k) {                                                \
            int idx = tid + (k << 10);                                               \
            int row = idx >> 4, c = idx & 15;                                        \
            uint4 v = __ldg((const uint4*)(g_pl + ((size_t)((TT) * 256 + row)) * BATCH + b0) + c); \
            *((uint4*)((BUF) + row * BT1) + c) = v;                                  \
        }                                                                            \
    }

    STAGE1(0, s_ed0, s_cn0);
    FILL1(0, pl0);
    __syncthreads();

    unsigned long long acc[8][2];
#pragma unroll
    for (int n = 0; n < 8; ++n) { acc[n][0] = 0ULL; acc[n][1] = 0ULL; }

    for (int t = 0; t < NT1; ++t) {
        // overlap: copy planes(t+1) + stage edges(t+1) with edge(t)
        if (t + 1 < NT1) {
            if (t & 1) { FILL1(t + 1, pl0); STAGE1(t + 1, s_ed0, s_cn0); }
            else       { FILL1(t + 1, pl1); STAGE1(t + 1, s_ed1, s_cn1); }
        }

        const char*     pcur = (const char*)((t & 1) ? pl1 : pl0) + lane * 8;
        const uint32_t* ebuf = (const uint32_t*)((t & 1) ? s_ed1 : s_ed0);
        const uint16_t* cbuf = (t & 1) ? s_cn1 : s_cn0;
#pragma unroll
        for (int n = 0; n < 8; ++n) {
            int rl = warp * 8 + n;
            int cnt = cbuf[rl];
            const uint32_t* ep = ebuf + rl * (ECAP1 / 2);
            int np = cnt >> 1;
            for (int j = 0; j < np; ++j) {
                uint32_t u = ep[j];
                uint2 va = *(const uint2*)(pcur + ((u & 0xffffu) << 8));
                uint2 vb = *(const uint2*)(pcur + ((u >> 16) << 8));
                float2 a0 = __half22float2(*(const __half2*)&va.x);
                float2 a1 = __half22float2(*(const __half2*)&va.y);
                float2 b0f = __half22float2(*(const __half2*)&vb.x);
                float2 b1f = __half22float2(*(const __half2*)&vb.y);
                addp(acc[n][0], f2u(a0)); addp(acc[n][1], f2u(a1));
                addp(acc[n][0], f2u(b0f)); addp(acc[n][1], f2u(b1f));
            }
            if (cnt & 1) {
                uint32_t u = ep[np] & 0xffffu;
                uint2 va = *(const uint2*)(pcur + (u << 8));
                float2 a0 = __half22float2(*(const __half2*)&va.x);
                float2 a1 = __half22float2(*(const __half2*)&va.y);
                addp(acc[n][0], f2u(a0)); addp(acc[n][1], f2u(a1));
            }
        }
        __syncthreads();
    }

    // epilogue: w * acc -> g_hT (fp32)
    float w = *wp;
#pragma unroll
    for (int n = 0; n < 8; ++n) {
        int r = r0 + warp * 8 + n;
        float2 lo = *(float2*)&acc[n][0];
        float2 hi = *(float2*)&acc[n][1];
        float4 q; q.x = w * lo.x; q.y = w * lo.y; q.z = w * hi.x; q.w = w * hi.y;
        *(float4*)&g_hT[(size_t)r * BATCH + b0 + lane * 4] = q;
    }
#undef STAGE1
#undef FILL1
}

// ------------------------------------------------------------------
// Layer 2: unchanged from R6/R8 (proven 116us). fp32 planes, SRCS=128,
// BT=64, reg-prefetched fill, two barriers per tile.
// ------------------------------------------------------------------
__global__ void __launch_bounds__(1024, 1)
layer2_kernel(const float* __restrict__ wp, float* __restrict__ dout) {
    extern __shared__ char smraw[];
    float*    planes = (float*)smraw;                           // 128KB
    uint16_t* s_ed0  = (uint16_t*)(smraw + 128 * 4 * BT2 * 4);
    uint16_t* s_ed1  = s_ed0 + 256 * ECAP2;
    uint16_t* s_cn0  = s_ed1 + 256 * ECAP2;
    uint16_t* s_cn1  = s_cn0 + 256;

    int b0   = blockIdx.x * BT2;
    int r0   = blockIdx.y * 256;
    int tid  = threadIdx.x;
    int warp = tid >> 5, lane = tid & 31;

#define STAGE2(TT, ED, CN)                                                            \
    {                                                                                 \
        const uint4* esrc = (const uint4*)(g_et2 + ((size_t)(TT) * OUT_DIM + r0) * ECAP2); \
        uint4* edst = (uint4*)(ED);                                                   \
        for (int i = tid; i < 256 * ECAP2 / 8; i += 1024) edst[i] = __ldg(esrc + i);  \
        const uint4* csrc = (const uint4*)(g_ct2 + (size_t)(TT) * OUT_DIM + r0);      \
        uint4* cdst = (uint4*)(CN);                                                   \
        for (int i = tid; i < 256 / 8; i += 1024) cdst[i] = __ldg(csrc + i);          \
    }

    STAGE2(0, s_ed0, s_cn0);

    unsigned long long acc[8];
#pragma unroll
    for (int n = 0; n < 8; ++n) acc[n] = 0ULL;

    float4 pf[2];
#define LOADF2(T)                                                                \
    {                                                                            \
        _Pragma("unroll")                                                        \
        for (int k = 0; k < 2; ++k) {                                            \
            int idx = tid + (k << 10);                                           \
            int ls = idx >> 4, c4 = (idx & 15) << 2;                             \
            int s0 = (T) * 128;                                                  \
            const float* gb = (s0 < IN_DIM)                                      \
                ? g_xT + (size_t)s0 * BATCH                                      \
                : g_hT + (size_t)(s0 - IN_DIM) * BATCH;                          \
            pf[k] = __ldg((const float4*)(gb + (size_t)ls * BATCH + b0 + c4));   \
        }                                                                        \
    }

    LOADF2(0);
    __syncthreads();

    const char* pbase = (const char*)planes + lane * 8;

    for (int t = 0; t < NT2; ++t) {
#pragma unroll
        for (int k = 0; k < 2; ++k) {
            int idx = tid + (k << 10);
            int ls = idx >> 4, c4 = (idx & 15) << 2;
            float4 xv = pf[k];
            float4 p1, p2, p3;
            p1.x = fmaxf(xv.x, 0.0f); p1.y = fmaxf(xv.y, 0.0f);
            p1.z = fmaxf(xv.z, 0.0f); p1.w = fmaxf(xv.w, 0.0f);
            p2.x = ftanh(xv.x); p2.y = ftanh(xv.y); p2.z = ftanh(xv.z); p2.w = ftanh(xv.w);
            p3.x = fmaf(0.5f, ftanh(0.5f * xv.x), 0.5f);
            p3.y = fmaf(0.5f, ftanh(0.5f * xv.y), 0.5f);
            p3.z = fmaf(0.5f, ftanh(0.5f * xv.z), 0.5f);
            p3.w = fmaf(0.5f, ftanh(0.5f * xv.w), 0.5f);
            float* pr = planes + (size_t)(ls * 4) * BT2 + c4;
            *(float4*)(pr)           = xv;
            *(float4*)(pr + BT2)     = p1;
            *(float4*)(pr + 2 * BT2) = p2;
            *(float4*)(pr + 3 * BT2) = p3;
        }
        if (t + 1 < NT2) {
            if (t & 1) STAGE2(t + 1, s_ed0, s_cn0)
            else       STAGE2(t + 1, s_ed1, s_cn1)
        }
        __syncthreads();

        if (t + 1 < NT2) LOADF2(t + 1);

        const uint32_t* ebuf = (const uint32_t*)((t & 1) ? s_ed1 : s_ed0);
        const uint16_t* cbuf = (t & 1) ? s_cn1 : s_cn0;
#pragma unroll
        for (int n = 0; n < 8; ++n) {
            int rl = warp * 8 + n;
            int cnt = cbuf[rl];
            const uint32_t* ep = ebuf + rl * (ECAP2 / 2);
            int np = cnt >> 1;
            for (int j = 0; j < np; ++j) {
                uint32_t u = ep[j];
                unsigned long long a = *(const unsigned long long*)(pbase + ((u & 0xffffu) << 8));
                unsigned long long b = *(const unsigned long long*)(pbase + ((u >> 16) << 8));
                addp(acc[n], a);
                addp(acc[n], b);
            }
            if (cnt & 1) {
                uint32_t u = ep[np] & 0xffffu;
                addp(acc[n], *(const unsigned long long*)(pbase + (u << 8)));
            }
        }
        __syncthreads();
    }

#pragma unroll
    for (int n = 0; n < 8; ++n) {
        int r = r0 + warp * 8 + n;
        float2 v = *(float2*)&acc[n];
        dout[(size_t)(b0 + lane * 2 + 0) * OUT_DIM + r] = v.x;
        dout[(size_t)(b0 + lane * 2 + 1) * OUT_DIM + r] = v.y;
    }
#undef STAGE2
#undef LOADF2
}

#define SMEM_L1 (131072 + 2 * 256 * ECAP1 * 2 + 2 * 256 * 2)            // 148480
#define SMEM_L2 (128 * 4 * BT2 * 4 + 2 * 256 * ECAP2 * 2 + 2 * 256 * 2) // 156672

extern "C" void kernel_launch(void* const* d_in, const int* in_sizes, int n_in,
                              void* d_out, int out_size) {
    const float* x   = (const float*)d_in[0];
    const float* wp  = (const float*)d_in[1];
    const int*   mat = (const int*)d_in[2];
    float*       out = (float*)d_out;

    cudaFuncSetAttribute(layer1_kernel, cudaFuncAttributeMaxDynamicSharedMemorySize, SMEM_L1);
    cudaFuncSetAttribute(layer2_kernel, cudaFuncAttributeMaxDynamicSharedMemorySize, SMEM_L2);

    build_edges_kernel<<<N_HID + OUT_DIM, 256>>>(mat);
    act_kernel<<<dim3(IN_DIM / 32, BATCH / 32), dim3(32, 8)>>>(x, wp);

    // L1: grid (row-tiles=8, batch=64): adjacent bids share a batch-tile
    // -> g_pl reads hit L2 (8x reuse)
    layer1_kernel<<<dim3(N_HID / 256, BATCH / BT1), 1024, SMEM_L1>>>(wp);

    // L2: unchanged R6 config
    layer2_kernel<<<dim3(BATCH / BT2, OUT_DIM / 256), 1024, SMEM_L2>>>(wp, out);
}

// round 10
// speedup vs baseline: 1.4846x; 1.0484x over previous
#include <cuda_runtime.h>
#include <cuda_fp16.h>
#include <stdint.h>

#define BATCH   8192
#define IN_DIM  1024
#define N_HID   2048
#define OUT_DIM 256
#define S2      3072
#define NT1     16        // 1024/64  source tiles (layer1, 64-wide)
#define NT2     24        // 3072/128 source tiles (layer2, 128-wide)
#define ECAP1   16        // Bin(64,.05):  mean 3.2, 7.3 sigma
#define ECAP2   24        // Bin(128,.05): mean 6.4, 7.1 sigma
#define BT2     64        // layer2 batch tile
#define BT1     128       // layer1 batch tile

// ---- scratch (static device globals: allocation-free) ----
__device__ float    g_xT[(size_t)IN_DIM * BATCH];                 // w * x, transposed (L2 fill)
__device__ float    g_hT[(size_t)N_HID * BATCH];                  // w * hidden, transposed
__device__ __half   g_pl[(size_t)IN_DIM * 4 * BATCH];             // 4 act planes of w*x, fp16
__device__ uint16_t g_et1[(size_t)NT1 * N_HID * ECAP1];           // [tile][row][ECAP1]
__device__ uint16_t g_et2[(size_t)NT2 * OUT_DIM * ECAP2];
__device__ uint16_t g_ct1[(size_t)NT1 * N_HID];                   // [tile][row]
__device__ uint16_t g_ct2[(size_t)NT2 * OUT_DIM];

// ---- cp.async helpers ----
__device__ __forceinline__ void cpa16(uint32_t dst, const void* src) {
    asm volatile("cp.async.cg.shared.global [%0], [%1], 16;" :: "r"(dst), "l"(src));
}
#define CP_COMMIT() asm volatile("cp.async.commit_group;")
#define CP_WAIT0()  asm volatile("cp.async.wait_group 0;")

__device__ __forceinline__ float ftanh(float x) {
    float r; asm("tanh.approx.f32 %0, %1;" : "=f"(r) : "f"(x)); return r;
}
__device__ __forceinline__ void addp(unsigned long long& a, unsigned long long b) {
    asm("add.rn.f32x2 %0, %0, %1;" : "+l"(a) : "l"(b));
}
__device__ __forceinline__ unsigned long long f2u(float2 v) {
    unsigned long long r; asm("mov.b64 %0, {%1,%2};" : "=l"(r) : "f"(v.x), "f"(v.y)); return r;
}

// ------------------------------------------------------------------
// Build tile-major edge lists. Entry = s_in_tile*4 + (code-1); layer
// kernels shift <<8 (plane row = 256B in both layers). Deterministic.
// ------------------------------------------------------------------
__global__ void build_edges_kernel(const int* __restrict__ mat) {
    int row  = blockIdx.x;
    int lane = threadIdx.x & 31, warp = threadIdx.x >> 5;  // 256 thr
    bool is2 = (row >= N_HID);
    int ntiles = is2 ? NT2 : NT1;
    int tw     = is2 ? 128 : 64;
    int ecap   = is2 ? ECAP2 : ECAP1;
    int rows   = is2 ? OUT_DIM : N_HID;
    int rloc   = is2 ? row - N_HID : row;
    const int* mrow = mat + (size_t)row * S2;
    uint16_t* et = is2 ? g_et2 : g_et1;
    uint16_t* ct = is2 ? g_ct2 : g_ct1;
    unsigned lt = (1u << lane) - 1u;

    for (int t = warp; t < ntiles; t += 8) {
        int cnt = 0;
        uint16_t* dst = et + ((size_t)t * rows + rloc) * ecap;
        for (int c = 0; c < tw / 32; ++c) {
            int code = mrow[t * tw + c * 32 + lane];
            unsigned m = __ballot_sync(0xffffffffu, code != 0);
            int p = cnt + __popc(m & lt);
            if (code && p < ecap)
                dst[p] = (uint16_t)(((c * 32 + lane) << 2) | (code - 1));
            cnt += __popc(m);
        }
        if (lane == 0) ct[(size_t)t * rows + rloc] = (uint16_t)(cnt < ecap ? cnt : ecap);
    }
}

// ------------------------------------------------------------------
// act_kernel: transpose x, scale by w, write g_xT (fp32) and the 4
// fp16 activation planes g_pl.
// ------------------------------------------------------------------
__global__ void act_kernel(const float* __restrict__ x, const float* __restrict__ wp) {
    __shared__ float tile[32][33];
    float w = *wp;
    int i0 = blockIdx.x * 32, b0 = blockIdx.y * 32;
    int tx = threadIdx.x, ty = threadIdx.y;   // 32 x 8
#pragma unroll
    for (int k = 0; k < 32; k += 8)
        tile[ty + k][tx] = w * x[(size_t)(b0 + ty + k) * IN_DIM + i0 + tx];
    __syncthreads();
#pragma unroll
    for (int k = 0; k < 32; k += 8) {
        int s = i0 + ty + k;
        int b = b0 + tx;
        float v = tile[tx][ty + k];
        g_xT[(size_t)s * BATCH + b] = v;
        size_t base = ((size_t)s * 4) * BATCH + b;
        g_pl[base]             = __float2half_rn(v);
        g_pl[base + BATCH]     = __float2half_rn(fmaxf(v, 0.0f));
        g_pl[base + 2 * BATCH] = __float2half_rn(ftanh(v));
        g_pl[base + 3 * BATCH] = __float2half_rn(fmaf(0.5f, ftanh(0.5f * v), 0.5f));
    }
}

// ------------------------------------------------------------------
// Layer 1: fp16 planes, double-buffered; ALL staging (planes + edges)
// via cp.async issued before edge(t), waited at tile-end barrier.
// ------------------------------------------------------------------
__global__ void __launch_bounds__(1024, 1)
layer1_kernel(const float* __restrict__ wp) {
    extern __shared__ char smraw[];
    // layout: pl0 64KB | pl1 64KB | ed0 8KB | ed1 8KB | cn0 512 | cn1 512
    uint32_t sbase = (uint32_t)__cvta_generic_to_shared(smraw);
    __half*   pl[2]; pl[0] = (__half*)smraw; pl[1] = pl[0] + 64 * 4 * BT1;
    uint16_t* ed[2]; ed[0] = (uint16_t*)(smraw + 131072); ed[1] = ed[0] + 256 * ECAP1;
    uint16_t* cn[2]; cn[0] = ed[1] + 256 * ECAP1; cn[1] = cn[0] + 256;
    uint32_t pl_a[2] = { sbase, sbase + 65536 };
    uint32_t ed_a[2] = { sbase + 131072, sbase + 131072 + 8192 };
    uint32_t cn_a[2] = { sbase + 147456, sbase + 147456 + 512 };

    int r0   = blockIdx.x * 256;
    int b0   = blockIdx.y * BT1;
    int tid  = threadIdx.x;
    int warp = tid >> 5, lane = tid & 31;

    // cp.async staging of tile TT into buffer B
#define STAGE1(TT, B)                                                                 \
    {                                                                                 \
        _Pragma("unroll")                                                             \
        for (int k = 0; k < 4; ++k) {                                                 \
            int idx = tid + (k << 10);                                                \
            int row = idx >> 4, c = idx & 15;                                         \
            cpa16(pl_a[B] + row * 256 + c * 16,                                       \
                  g_pl + ((size_t)((TT) * 256 + row)) * BATCH + b0 + c * 8);          \
        }                                                                             \
        if (tid < 512)                                                                \
            cpa16(ed_a[B] + tid * 16,                                                 \
                  g_et1 + ((size_t)(TT) * N_HID + r0) * ECAP1 + tid * 8);             \
        if (tid < 32)                                                                 \
            cpa16(cn_a[B] + tid * 16, g_ct1 + (size_t)(TT) * N_HID + r0 + tid * 8);   \
    }

    STAGE1(0, 0);
    CP_COMMIT();
    CP_WAIT0();
    __syncthreads();

    unsigned long long acc[8][2];
#pragma unroll
    for (int n = 0; n < 8; ++n) { acc[n][0] = 0ULL; acc[n][1] = 0ULL; }

    for (int t = 0; t < NT1; ++t) {
        int cur = t & 1;
        // fire-and-forget staging of tile t+1 (no register hold, no stall)
        if (t + 1 < NT1) { STAGE1(t + 1, cur ^ 1); }
        CP_COMMIT();

        const char*     pcur = (const char*)pl[cur] + lane * 8;
        const uint32_t* ebuf = (const uint32_t*)ed[cur];
        const uint16_t* cbuf = cn[cur];
#pragma unroll
        for (int n = 0; n < 8; ++n) {
            int rl = warp * 8 + n;
            int cnt = cbuf[rl];
            const uint32_t* ep = ebuf + rl * (ECAP1 / 2);
            int np = cnt >> 1;
            for (int j = 0; j < np; ++j) {
                uint32_t u = ep[j];
                uint2 va = *(const uint2*)(pcur + ((u & 0xffffu) << 8));
                uint2 vb = *(const uint2*)(pcur + ((u >> 16) << 8));
                float2 a0 = __half22float2(*(const __half2*)&va.x);
                float2 a1 = __half22float2(*(const __half2*)&va.y);
                float2 b0f = __half22float2(*(const __half2*)&vb.x);
                float2 b1f = __half22float2(*(const __half2*)&vb.y);
                addp(acc[n][0], f2u(a0)); addp(acc[n][1], f2u(a1));
                addp(acc[n][0], f2u(b0f)); addp(acc[n][1], f2u(b1f));
            }
            if (cnt & 1) {
                uint32_t u = ep[np] & 0xffffu;
                uint2 va = *(const uint2*)(pcur + (u << 8));
                float2 a0 = __half22float2(*(const __half2*)&va.x);
                float2 a1 = __half22float2(*(const __half2*)&va.y);
                addp(acc[n][0], f2u(a0)); addp(acc[n][1], f2u(a1));
            }
        }
        CP_WAIT0();        // tile t+1 staging complete
        __syncthreads();
    }

    float w = *wp;
#pragma unroll
    for (int n = 0; n < 8; ++n) {
        int r = r0 + warp * 8 + n;
        float2 lo = *(float2*)&acc[n][0];
        float2 hi = *(float2*)&acc[n][1];
        float4 q; q.x = w * lo.x; q.y = w * lo.y; q.z = w * hi.x; q.w = w * hi.y;
        *(float4*)&g_hT[(size_t)r * BATCH + b0 + lane * 4] = q;
    }
#undef STAGE1
}

// ------------------------------------------------------------------
// Layer 2: R6 structure (fp32 planes, reg-prefetch fill); edge staging
// converted to cp.async.
// ------------------------------------------------------------------
__global__ void __launch_bounds__(1024, 1)
layer2_kernel(const float* __restrict__ wp, float* __restrict__ dout) {
    extern __shared__ char smraw[];
    uint32_t sbase = (uint32_t)__cvta_generic_to_shared(smraw);
    float*    planes = (float*)smraw;                           // 128KB
    uint16_t* ed[2]; ed[0] = (uint16_t*)(smraw + 131072); ed[1] = ed[0] + 256 * ECAP2;
    uint16_t* cn[2]; cn[0] = ed[1] + 256 * ECAP2;          cn[1] = cn[0] + 256;
    uint32_t ed_a[2] = { sbase + 131072, sbase + 131072 + 256 * ECAP2 * 2 };
    uint32_t cn_a[2] = { sbase + 131072 + 2 * 256 * ECAP2 * 2,
                         sbase + 131072 + 2 * 256 * ECAP2 * 2 + 512 };

    int b0   = blockIdx.x * BT2;
    int r0   = blockIdx.y * 256;
    int tid  = threadIdx.x;
    int warp = tid >> 5, lane = tid & 31;

#define STAGE2(TT, B)                                                                 \
    {                                                                                 \
        if (tid < 768)                                                                \
            cpa16(ed_a[B] + tid * 16,                                                 \
                  g_et2 + ((size_t)(TT) * OUT_DIM + r0) * ECAP2 + tid * 8);           \
        if (tid < 32)                                                                 \
            cpa16(cn_a[B] + tid * 16, g_ct2 + (size_t)(TT) * OUT_DIM + r0 + tid * 8); \
    }

    STAGE2(0, 0);
    CP_COMMIT();

    unsigned long long acc[8];
#pragma unroll
    for (int n = 0; n < 8; ++n) acc[n] = 0ULL;

    float4 pf[2];
#define LOADF2(T)                                                                \
    {                                                                            \
        _Pragma("unroll")                                                        \
        for (int k = 0; k < 2; ++k) {                                            \
            int idx = tid + (k << 10);                                           \
            int ls = idx >> 4, c4 = (idx & 15) << 2;                             \
            int s0 = (T) * 128;                                                  \
            const float* gb = (s0 < IN_DIM)                                      \
                ? g_xT + (size_t)s0 * BATCH                                      \
                : g_hT + (size_t)(s0 - IN_DIM) * BATCH;                          \
            pf[k] = __ldg((const float4*)(gb + (size_t)ls * BATCH + b0 + c4));   \
        }                                                                        \
    }

    LOADF2(0);
    CP_WAIT0();
    __syncthreads();

    const char* pbase = (const char*)planes + lane * 8;

    for (int t = 0; t < NT2; ++t) {
        int cur = t & 1;
#pragma unroll
        for (int k = 0; k < 2; ++k) {
            int idx = tid + (k << 10);
            int ls = idx >> 4, c4 = (idx & 15) << 2;
            float4 xv = pf[k];
            float4 p1, p2, p3;
            p1.x = fmaxf(xv.x, 0.0f); p1.y = fmaxf(xv.y, 0.0f);
            p1.z = fmaxf(xv.z, 0.0f); p1.w = fmaxf(xv.w, 0.0f);
            p2.x = ftanh(xv.x); p2.y = ftanh(xv.y); p2.z = ftanh(xv.z); p2.w = ftanh(xv.w);
            p3.x = fmaf(0.5f, ftanh(0.5f * xv.x), 0.5f);
            p3.y = fmaf(0.5f, ftanh(0.5f * xv.y), 0.5f);
            p3.z = fmaf(0.5f, ftanh(0.5f * xv.z), 0.5f);
            p3.w = fmaf(0.5f, ftanh(0.5f * xv.w), 0.5f);
            float* pr = planes + (size_t)(ls * 4) * BT2 + c4;
            *(float4*)(pr)           = xv;
            *(float4*)(pr + BT2)     = p1;
            *(float4*)(pr + 2 * BT2) = p2;
            *(float4*)(pr + 3 * BT2) = p3;
        }
        if (t + 1 < NT2) { STAGE2(t + 1, cur ^ 1); }
        CP_COMMIT();
        __syncthreads();   // planes(t) ready

        if (t + 1 < NT2) LOADF2(t + 1);

        const uint32_t* ebuf = (const uint32_t*)ed[cur];
        const uint16_t* cbuf = cn[cur];
#pragma unroll
        for (int n = 0; n < 8; ++n) {
            int rl = warp * 8 + n;
            int cnt = cbuf[rl];
            const uint32_t* ep = ebuf + rl * (ECAP2 / 2);
            int np = cnt >> 1;
            for (int j = 0; j < np; ++j) {
                uint32_t u = ep[j];
                unsigned long long a = *(const unsigned long long*)(pbase + ((u & 0xffffu) << 8));
                unsigned long long b = *(const unsigned long long*)(pbase + ((u >> 16) << 8));
                addp(acc[n], a);
                addp(acc[n], b);
            }
            if (cnt & 1) {
                uint32_t u = ep[np] & 0xffffu;
                addp(acc[n], *(const unsigned long long*)(pbase + (u << 8)));
            }
        }
        CP_WAIT0();        // edges(t+1) staged
        __syncthreads();
    }

#pragma unroll
    for (int n = 0; n < 8; ++n) {
        int r = r0 + warp * 8 + n;
        float2 v = *(float2*)&acc[n];
        dout[(size_t)(b0 + lane * 2 + 0) * OUT_DIM + r] = v.x;
        dout[(size_t)(b0 + lane * 2 + 1) * OUT_DIM + r] = v.y;
    }
#undef STAGE2
#undef LOADF2
}

#define SMEM_L1 (131072 + 2 * 256 * ECAP1 * 2 + 2 * 256 * 2)            // 148480
#define SMEM_L2 (131072 + 2 * 256 * ECAP2 * 2 + 2 * 256 * 2)            // 156672

extern "C" void kernel_launch(void* const* d_in, const int* in_sizes, int n_in,
                              void* d_out, int out_size) {
    const float* x   = (const float*)d_in[0];
    const float* wp  = (const float*)d_in[1];
    const int*   mat = (const int*)d_in[2];
    float*       out = (float*)d_out;

    cudaFuncSetAttribute(layer1_kernel, cudaFuncAttributeMaxDynamicSharedMemorySize, SMEM_L1);
    cudaFuncSetAttribute(layer2_kernel, cudaFuncAttributeMaxDynamicSharedMemorySize, SMEM_L2);

    build_edges_kernel<<<N_HID + OUT_DIM, 256>>>(mat);
    act_kernel<<<dim3(IN_DIM / 32, BATCH / 32), dim3(32, 8)>>>(x, wp);

    // L1: adjacent bids share a batch-tile -> g_pl L2-resident (64MB < 126MB L2)
    layer1_kernel<<<dim3(N_HID / 256, BATCH / BT1), 1024, SMEM_L1>>>(wp);

    layer2_kernel<<<dim3(BATCH / BT2, OUT_DIM / 256), 1024, SMEM_L2>>>(wp, out);
}